// round 7
// baseline (speedup 1.0000x reference)
#include <cuda_runtime.h>
#include <cstdint>

#define NNODES 50000
#define MAXEDGES 800000
#define HID 128
#define EMB 64
#define KCLUS 10

typedef unsigned long long u64;

// packed fp32 FMA: d.lo = a.lo*b.lo + c.lo ; d.hi = a.hi*b.hi + c.hi  (IEEE fp32 each lane)
#define FFMA2(d, a, b, c) \
    asm("fma.rn.f32x2 %0, %1, %2, %3;" : "=l"(d) : "l"(a), "l"(b), "l"(c))
#define PACK2(out, lo, hi) \
    asm("mov.b64 %0, {%1, %2};" : "=l"(out) : "f"(lo), "f"(hi))
#define UNPACK2(lo, hi, in) \
    asm("mov.b64 {%0, %1}, %2;" : "=f"(lo), "=f"(hi) : "l"(in))

// ---------------- scratch (device globals; no allocation allowed) ----------------
__device__ float g_xw  [NNODES * HID];        // x @ w1
__device__ float g_h   [NNODES * HID];        // relu(spmm + b1)
__device__ float g_hw  [NNODES * EMB];        // h @ w2
__device__ float g_zcat[NNODES * 3 * EMB];    // concat(z0,z1,z2)
__device__ int   g_cnt [NNODES];
__device__ int   g_off [NNODES + 1];
__device__ int   g_cur [NNODES];
__device__ int   g_scols[MAXEDGES];
__device__ float g_svals[MAXEDGES];
__device__ int   g_bsum[64];                  // block sums for hierarchical scan

// ---------------- tiled fp32 SGEMM with packed FFMA2 ---------------------------
// BM=128, BN=64, BK=8, 256 threads, thread tile 8x4 (row-paired accumulators).
// Bs stored duplicated (b,b per value) so b-broadcast pairs load directly as LDS.
#define BM 128
#define BN 64
#define BK 8
#define TM 8
#define TN 4

template<bool EPI_BIAS_RELU>
__global__ void __launch_bounds__(256)
sgemm_kernel(const float* __restrict__ A, const float* __restrict__ B,
             const float* __restrict__ bias, float* __restrict__ C,
             int M, int K, int nc)
{
    __shared__ float As [BK][BM];
    __shared__ float Bs2[BK][BN * 2];   // duplicated: [b0,b0,b1,b1,...]

    const int tid = threadIdx.x;
    const int bm  = blockIdx.x * BM;
    const int bn  = blockIdx.y * BN;
    const int tx  = tid & 15;     // 0..15 -> n offset tx*4
    const int ty  = tid >> 4;     // 0..15 -> m offset ty*8

    // acc2[i2][j] = (acc[2*i2][j], acc[2*i2+1][j]) packed fp32x2
    u64 acc2[4][4];
    #pragma unroll
    for (int i = 0; i < 4; i++)
        #pragma unroll
        for (int j = 0; j < 4; j++) acc2[i][j] = 0ull;

    // A tile load mapping: 128 rows x 8 k, one float4 per thread
    const int arow = tid >> 1;            // 0..127
    const int acol = (tid & 1) * 4;       // 0 or 4
    // B tile load mapping: 8 rows x 64 cols, one float2 per thread
    const int brow = tid >> 5;            // 0..7
    const int bcol = (tid & 31) * 2;      // 0..62

    const bool avalid = (bm + arow) < M;
    const float* Abase = A + (size_t)(bm + arow) * K + acol;
    const float* Bbase = B + (size_t)brow * nc + bn + bcol;

    for (int k0 = 0; k0 < K; k0 += BK) {
        float4 av = make_float4(0.f, 0.f, 0.f, 0.f);
        if (avalid) av = *(const float4*)(Abase + k0);
        As[acol + 0][arow] = av.x;
        As[acol + 1][arow] = av.y;
        As[acol + 2][arow] = av.z;
        As[acol + 3][arow] = av.w;

        float2 bv = *(const float2*)(Bbase + (size_t)k0 * nc);
        // duplicated store: one float4 = (x,x,y,y)
        *(float4*)&Bs2[brow][bcol * 2] = make_float4(bv.x, bv.x, bv.y, bv.y);
        __syncthreads();

        #pragma unroll
        for (int kk = 0; kk < BK; kk++) {
            // a row-pairs alias directly from LDS.128 (consecutive rows)
            ulonglong2 aA = *(const ulonglong2*)&As[kk][ty * TM];
            ulonglong2 aB = *(const ulonglong2*)&As[kk][ty * TM + 4];
            // b broadcast-pairs alias directly from duplicated LDS.128
            ulonglong2 bA = *(const ulonglong2*)&Bs2[kk][tx * TN * 2];
            ulonglong2 bB = *(const ulonglong2*)&Bs2[kk][tx * TN * 2 + 4];
            u64 a2[4] = {aA.x, aA.y, aB.x, aB.y};
            u64 b2[4] = {bA.x, bA.y, bB.x, bB.y};
            #pragma unroll
            for (int i = 0; i < 4; i++)
                #pragma unroll
                for (int j = 0; j < 4; j++)
                    FFMA2(acc2[i][j], a2[i], b2[j], acc2[i][j]);
        }
        __syncthreads();
    }

    float bvv[TN] = {0.f, 0.f, 0.f, 0.f};
    if (EPI_BIAS_RELU) {
        #pragma unroll
        for (int j = 0; j < TN; j++) bvv[j] = bias[bn + tx * TN + j];
    }

    #pragma unroll
    for (int i2 = 0; i2 < 4; i2++) {
        float lo[4], hi[4];
        #pragma unroll
        for (int j = 0; j < 4; j++) UNPACK2(lo[j], hi[j], acc2[i2][j]);

        int r0 = bm + ty * TM + 2 * i2;
        int r1 = r0 + 1;
        if (r0 < M) {
            float v0 = lo[0], v1 = lo[1], v2 = lo[2], v3 = lo[3];
            if (EPI_BIAS_RELU) {
                v0 = fmaxf(v0 + bvv[0], 0.f); v1 = fmaxf(v1 + bvv[1], 0.f);
                v2 = fmaxf(v2 + bvv[2], 0.f); v3 = fmaxf(v3 + bvv[3], 0.f);
            }
            *(float4*)(C + (size_t)r0 * nc + bn + tx * TN) = make_float4(v0, v1, v2, v3);
        }
        if (r1 < M) {
            float v0 = hi[0], v1 = hi[1], v2 = hi[2], v3 = hi[3];
            if (EPI_BIAS_RELU) {
                v0 = fmaxf(v0 + bvv[0], 0.f); v1 = fmaxf(v1 + bvv[1], 0.f);
                v2 = fmaxf(v2 + bvv[2], 0.f); v3 = fmaxf(v3 + bvv[3], 0.f);
            }
            *(float4*)(C + (size_t)r1 * nc + bn + tx * TN) = make_float4(v0, v1, v2, v3);
        }
    }
}

// =================================================================================
// CSR construction: count -> hierarchical scan (3 kernels) -> scatter
// =================================================================================
__global__ void zero_kernel(int* p, int n)
{
    int i = blockIdx.x * blockDim.x + threadIdx.x;
    if (i < n) p[i] = 0;
}

__global__ void count_kernel(const int* __restrict__ rows, int* __restrict__ cnt, int E)
{
    int e = blockIdx.x * blockDim.x + threadIdx.x;
    if (e < E) atomicAdd(&cnt[rows[e]], 1);
}

// Phase 1: per-block (1024 elems) sum
__global__ void __launch_bounds__(256)
deg_reduce(const int* __restrict__ cnt, int* __restrict__ bsum, int n)
{
    __shared__ int sh[256];
    int t = threadIdx.x;
    int base = blockIdx.x * 1024 + t * 4;
    int s = 0;
    if (base + 3 < n) {
        int4 v = *(const int4*)(cnt + base);
        s = v.x + v.y + v.z + v.w;
    } else {
        for (int i = 0; i < 4; i++) if (base + i < n) s += cnt[base + i];
    }
    sh[t] = s;
    __syncthreads();
    for (int d = 128; d > 0; d >>= 1) {
        if (t < d) sh[t] += sh[t + d];
        __syncthreads();
    }
    if (t == 0) bsum[blockIdx.x] = sh[0];
}

// Phase 2: exclusive scan of block sums (nb <= 256), single block
__global__ void __launch_bounds__(256)
scan_bsums(int* bsum, int nb)
{
    __shared__ int sh[256];
    int t = threadIdx.x;
    int v = (t < nb) ? bsum[t] : 0;
    sh[t] = v;
    __syncthreads();
    for (int d = 1; d < 256; d <<= 1) {
        int u = (t >= d) ? sh[t - d] : 0;
        __syncthreads();
        sh[t] += u;
        __syncthreads();
    }
    if (t < nb) bsum[t] = sh[t] - v;   // exclusive
}

// Phase 3: per-block scan + add prefix, emit off[] and cur[]
__global__ void __launch_bounds__(256)
scan_apply(const int* __restrict__ cnt, const int* __restrict__ bsum,
           int* __restrict__ off, int* __restrict__ cur, int n, int E)
{
    __shared__ int sh[256];
    int t = threadIdx.x;
    int base = blockIdx.x * 1024 + t * 4;
    int c[4];
    int s = 0;
    #pragma unroll
    for (int i = 0; i < 4; i++) {
        c[i] = (base + i < n) ? cnt[base + i] : 0;
        s += c[i];
    }
    sh[t] = s;
    __syncthreads();
    for (int d = 1; d < 256; d <<= 1) {
        int u = (t >= d) ? sh[t - d] : 0;
        __syncthreads();
        sh[t] += u;
        __syncthreads();
    }
    int pre = bsum[blockIdx.x] + sh[t] - s;
    #pragma unroll
    for (int i = 0; i < 4; i++) {
        if (base + i < n) {
            off[base + i] = pre;
            cur[base + i] = pre;
            pre += c[i];
        }
    }
    if (blockIdx.x == 0 && t == 0) off[n] = E;
}

__global__ void scatter_kernel(const int* __restrict__ rows, const int* __restrict__ cols,
                               const float* __restrict__ vals, int* __restrict__ cur,
                               int* __restrict__ scols, float* __restrict__ svals, int E)
{
    int e = blockIdx.x * blockDim.x + threadIdx.x;
    if (e < E) {
        int p = atomicAdd(&cur[rows[e]], 1);
        scols[p] = cols[e];
        svals[p] = vals[e];
    }
}

// ---------------- row-per-warp SpMM (packed f32x2 lanes) -------------------------
// lane owns column pairs {2*lane, 2*lane+1} + {64+2*lane, ...}; LDG.64 gathers.
template<int NC, bool RELU>
__global__ void __launch_bounds__(256)
spmm_kernel(const int* __restrict__ off, const int* __restrict__ scols,
            const float* __restrict__ svals, const float* __restrict__ dense,
            const float* __restrict__ bias,
            float* __restrict__ out, int ldo,
            float* __restrict__ out2, int ldo2, int n)
{
    const int warp = (blockIdx.x * blockDim.x + threadIdx.x) >> 5;
    const int lane = threadIdx.x & 31;
    if (warp >= n) return;

    const int s = off[warp];
    const int e = off[warp + 1];
    constexpr int V2 = NC / 64;         // pairs per lane (HID:2, EMB:1)

    u64 acc2[V2];
    #pragma unroll
    for (int i = 0; i < V2; i++) acc2[i] = 0ull;

    const int cbase = 2 * lane;

    int j = s;
    for (; j + 1 < e; j += 2) {
        const int   c0 = scols[j],   c1 = scols[j + 1];
        const float f0 = svals[j],   f1 = svals[j + 1];
        u64 v0, v1;
        PACK2(v0, f0, f0);
        PACK2(v1, f1, f1);
        const float* d0 = dense + (size_t)c0 * NC + cbase;
        const float* d1 = dense + (size_t)c1 * NC + cbase;
        #pragma unroll
        for (int i = 0; i < V2; i++) {
            u64 x0 = *(const u64*)(d0 + 64 * i);
            u64 x1 = *(const u64*)(d1 + 64 * i);
            FFMA2(acc2[i], v0, x0, acc2[i]);
            FFMA2(acc2[i], v1, x1, acc2[i]);
        }
    }
    if (j < e) {
        const int   c = scols[j];
        const float f = svals[j];
        u64 v;
        PACK2(v, f, f);
        const float* dr = dense + (size_t)c * NC + cbase;
        #pragma unroll
        for (int i = 0; i < V2; i++) {
            u64 x = *(const u64*)(dr + 64 * i);
            FFMA2(acc2[i], v, x, acc2[i]);
        }
    }

    #pragma unroll
    for (int i = 0; i < V2; i++) {
        float lo, hi;
        UNPACK2(lo, hi, acc2[i]);
        float r0 = lo + bias[cbase + 64 * i];
        float r1 = hi + bias[cbase + 64 * i + 1];
        if (RELU) { r0 = fmaxf(r0, 0.f); r1 = fmaxf(r1, 0.f); }
        *(float2*)(out + (size_t)warp * ldo + cbase + 64 * i) = make_float2(r0, r1);
        if (out2)
            *(float2*)(out2 + (size_t)warp * ldo2 + cbase + 64 * i) = make_float2(r0, r1);
    }
}

// ---------------- DEC soft assignment q ----------------
__global__ void __launch_bounds__(256)
q_kernel(const float* __restrict__ zf, const float* __restrict__ cluster,
         float* __restrict__ q, int n)
{
    __shared__ float cs[KCLUS * EMB];
    for (int i = threadIdx.x; i < KCLUS * EMB; i += blockDim.x) cs[i] = cluster[i];
    __syncthreads();

    int nid = blockIdx.x * blockDim.x + threadIdx.x;
    if (nid >= n) return;

    float z[EMB];
    const float* zr = zf + (size_t)nid * EMB;
    #pragma unroll
    for (int i = 0; i < EMB; i++) z[i] = zr[i];

    float qq[KCLUS];
    float s = 0.f;
    #pragma unroll
    for (int k = 0; k < KCLUS; k++) {
        float d = 0.f;
        #pragma unroll
        for (int i = 0; i < EMB; i++) {
            float diff = z[i] - cs[k * EMB + i];
            d = fmaf(diff, diff, d);
        }
        qq[k] = 1.f / (1.f + d);
        s += qq[k];
    }
    float inv = 1.f / s;
    #pragma unroll
    for (int k = 0; k < KCLUS; k++)
        q[(size_t)nid * KCLUS + k] = qq[k] * inv;
}

// ---------------- host launcher ----------------
extern "C" void kernel_launch(void* const* d_in, const int* in_sizes, int n_in,
                              void* d_out, int out_size)
{
    float *xw, *h, *hw, *zcat, *svals;
    int *cnt, *off, *cur, *scols, *bsum;
    cudaGetSymbolAddress((void**)&xw,    g_xw);
    cudaGetSymbolAddress((void**)&h,     g_h);
    cudaGetSymbolAddress((void**)&hw,    g_hw);
    cudaGetSymbolAddress((void**)&zcat,  g_zcat);
    cudaGetSymbolAddress((void**)&cnt,   g_cnt);
    cudaGetSymbolAddress((void**)&off,   g_off);
    cudaGetSymbolAddress((void**)&cur,   g_cur);
    cudaGetSymbolAddress((void**)&scols, g_scols);
    cudaGetSymbolAddress((void**)&svals, g_svals);
    cudaGetSymbolAddress((void**)&bsum,  g_bsum);

    float* out = (float*)d_out;
    const int N = NNODES;

    // Input ordering detection (dict order vs reference-signature order).
    int IX[3], IR[3], IC[3], IV[3], IW1[3], IB1[3], IW2[3], IB2[3], IFW, IFB, ICL;
    bool dictOrder = (n_in >= 3) && (in_sizes[1] == in_sizes[2]) && (in_sizes[1] < in_sizes[0]);
    if (dictOrder) {
        for (int v = 0; v < 3; v++) {
            IX[v] = 8 * v + 0; IR[v] = 8 * v + 1; IC[v] = 8 * v + 2; IV[v] = 8 * v + 3;
            IW1[v] = 8 * v + 4; IB1[v] = 8 * v + 5; IW2[v] = 8 * v + 6; IB2[v] = 8 * v + 7;
        }
        IFW = 24; IFB = 25; ICL = 26;
    } else {
        for (int v = 0; v < 3; v++) {
            IX[v] = v;
            IR[v] = 3 + 3 * v; IC[v] = 4 + 3 * v; IV[v] = 5 + 3 * v;
            IW1[v] = 12 + 4 * v; IB1[v] = 13 + 4 * v; IW2[v] = 14 + 4 * v; IB2[v] = 15 + 4 * v;
        }
        IFW = 24; IFB = 25; ICL = 26;
    }

    for (int v = 0; v < 3; v++) {
        const float* x    = (const float*)d_in[IX[v]];
        const int*   rows = (const int*)  d_in[IR[v]];
        const int*   cols = (const int*)  d_in[IC[v]];
        const float* vals = (const float*)d_in[IV[v]];
        const float* w1   = (const float*)d_in[IW1[v]];
        const float* b1   = (const float*)d_in[IB1[v]];
        const float* w2   = (const float*)d_in[IW2[v]];
        const float* b2   = (const float*)d_in[IB2[v]];
        const int din = in_sizes[IX[v]] / N;
        const int E   = in_sizes[IR[v]];
        const int nb  = (N + 1023) / 1024;

        // GEMM1: xw = x @ w1   [N, HID]
        {
            dim3 grid((N + BM - 1) / BM, HID / BN);
            sgemm_kernel<false><<<grid, 256>>>(x, w1, nullptr, xw, N, din, HID);
        }
        // CSR build (hierarchical scan)
        zero_kernel<<<(N + 255) / 256, 256>>>(cnt, N);
        count_kernel<<<(E + 255) / 256, 256>>>(rows, cnt, E);
        deg_reduce<<<nb, 256>>>(cnt, bsum, N);
        scan_bsums<<<1, 256>>>(bsum, nb);
        scan_apply<<<nb, 256>>>(cnt, bsum, off, cur, N, E);
        scatter_kernel<<<(E + 255) / 256, 256>>>(rows, cols, vals, cur, scols, svals, E);
        // SpMM1 + bias + relu -> h [N, HID]
        spmm_kernel<HID, true><<<(N + 7) / 8, 256>>>(off, scols, svals, xw, b1,
                                                     h, HID, nullptr, 0, N);
        // GEMM2: hw = h @ w2  [N, EMB]
        {
            dim3 grid((N + BM - 1) / BM, EMB / BN);
            sgemm_kernel<false><<<grid, 256>>>(h, w2, nullptr, hw, N, HID, EMB);
        }
        // SpMM2 + bias -> z_v, dual-write into d_out and concat buffer
        spmm_kernel<EMB, false><<<(N + 7) / 8, 256>>>(off, scols, svals, hw, b2,
                                                      out + (size_t)v * N * EMB, EMB,
                                                      zcat + (size_t)v * EMB, 3 * EMB, N);
    }

    const float* fw = (const float*)d_in[IFW];
    const float* fb = (const float*)d_in[IFB];
    const float* cl = (const float*)d_in[ICL];
    float* zf = out + (size_t)3 * N * EMB;
    float* qp = out + (size_t)4 * N * EMB;

    // fusion: zf = relu(zcat @ fusion_w + fusion_b)  [N, EMB]
    {
        dim3 grid((N + BM - 1) / BM, EMB / BN);
        sgemm_kernel<true><<<grid, 256>>>(zcat, fw, fb, zf, N, 3 * EMB, EMB);
    }
    // Student-t soft assignment
    q_kernel<<<(N + 255) / 256, 256>>>(zf, cl, qp, N);
}

// round 11
// speedup vs baseline: 2.5422x; 2.5422x over previous
#include <cuda_runtime.h>
#include <cuda_bf16.h>
#include <cstdint>

#define NNODES 50000
#define MAXEDGES 800000
#define HID 128
#define EMB 64
#define KCLUS 10
#define KPADMAX 1024

// ---------------- scratch (device globals; no allocation allowed) ----------------
__device__ float g_xw  [NNODES * HID];        // x @ w1
__device__ float g_h   [NNODES * HID];        // relu(spmm + b1)
__device__ float g_hw  [NNODES * EMB];        // h @ w2
__device__ float g_zcat[NNODES * 3 * EMB];    // concat(z0,z1,z2)
__device__ int   g_cnt [NNODES];
__device__ int   g_off [NNODES + 1];
__device__ int   g_cur [NNODES];
__device__ int   g_scols[MAXEDGES];
__device__ float g_svals[MAXEDGES];
__device__ int   g_bsum[64];
// bf16 split buffers for tensor GEMM1
__device__ __nv_bfloat16 g_xhi [NNODES * KPADMAX];
__device__ __nv_bfloat16 g_xlo [NNODES * KPADMAX];
__device__ __nv_bfloat16 g_wThi[HID * KPADMAX];
__device__ __nv_bfloat16 g_wTlo[HID * KPADMAX];

// =================================================================================
// fp32 -> bf16 hi/lo split conversion
// =================================================================================
__global__ void __launch_bounds__(256)
convx_kernel(const float* __restrict__ x, __nv_bfloat16* __restrict__ hi,
             __nv_bfloat16* __restrict__ lo, int Mrows, int din, int Kpad)
{
    int idx = blockIdx.x * blockDim.x + threadIdx.x;
    int half = Kpad >> 1;
    if (idx >= Mrows * half) return;
    int row = idx / half;
    int c   = (idx - row * half) * 2;

    float v0 = (c     < din) ? x[(size_t)row * din + c]     : 0.f;
    float v1 = (c + 1 < din) ? x[(size_t)row * din + c + 1] : 0.f;
    __nv_bfloat16 h0 = __float2bfloat16(v0);
    __nv_bfloat16 h1 = __float2bfloat16(v1);
    __nv_bfloat16 l0 = __float2bfloat16(v0 - __bfloat162float(h0));
    __nv_bfloat16 l1 = __float2bfloat16(v1 - __bfloat162float(h1));
    size_t o = (size_t)row * KPADMAX + c;
    *(__nv_bfloat162*)(hi + o) = __nv_bfloat162(h0, h1);
    *(__nv_bfloat162*)(lo + o) = __nv_bfloat162(l0, l1);
}

// transpose + split: wT[n][k] = w1[k][n], zero-padded to Kpad
__global__ void __launch_bounds__(256)
convw_kernel(const float* __restrict__ w1, __nv_bfloat16* __restrict__ hiT,
             __nv_bfloat16* __restrict__ loT, int din, int Kpad)
{
    int idx = blockIdx.x * blockDim.x + threadIdx.x;
    if (idx >= HID * Kpad) return;
    int n = idx / Kpad;
    int k = idx - n * Kpad;
    float v = (k < din) ? w1[(size_t)k * HID + n] : 0.f;
    __nv_bfloat16 h = __float2bfloat16(v);
    __nv_bfloat16 l = __float2bfloat16(v - __bfloat162float(h));
    hiT[(size_t)n * KPADMAX + k] = h;
    loT[(size_t)n * KPADMAX + k] = l;
}

// =================================================================================
// GEMM1 via mma.sync.m16n8k16 bf16, split hi/lo 3-pass (fp32 accumulate).
// CTA tile 128x64, K-chunks of 32. 8 warps: wm(2) x wn(4); warp tile 64x16.
// smem stride 40 bf16 -> all fragment LDS.32 conflict-free.
// =================================================================================
#define SMST 40

#define MMA16816(c, a, b)                                                     \
    asm volatile(                                                             \
        "mma.sync.aligned.m16n8k16.row.col.f32.bf16.bf16.f32 "                \
        "{%0,%1,%2,%3}, {%4,%5,%6,%7}, {%8,%9}, {%0,%1,%2,%3};"               \
        : "+f"((c)[0]), "+f"((c)[1]), "+f"((c)[2]), "+f"((c)[3])              \
        : "r"((a)[0]), "r"((a)[1]), "r"((a)[2]), "r"((a)[3]),                 \
          "r"((b)[0]), "r"((b)[1]))

__global__ void __launch_bounds__(256)
gemm1_mma(const uint16_t* __restrict__ Ahi, const uint16_t* __restrict__ Alo,
          const uint16_t* __restrict__ Bhi, const uint16_t* __restrict__ Blo,
          float* __restrict__ C, int M, int nChunk)
{
    __shared__ __align__(16) uint16_t sAh[128 * SMST];
    __shared__ __align__(16) uint16_t sAl[128 * SMST];
    __shared__ __align__(16) uint16_t sBh[64 * SMST];
    __shared__ __align__(16) uint16_t sBl[64 * SMST];

    const int tid  = threadIdx.x;
    const int lane = tid & 31;
    const int wid  = tid >> 5;
    const int wm   = wid >> 2;        // 0..1 -> 64 rows
    const int wn   = wid & 3;         // 0..3 -> 16 cols
    const int g    = lane >> 2;       // 0..7
    const int t    = lane & 3;        // 0..3
    const int bm   = blockIdx.x * 128;
    const int bn   = blockIdx.y * 64;

    float acc[4][2][4];
    #pragma unroll
    for (int i = 0; i < 4; i++)
        #pragma unroll
        for (int j = 0; j < 2; j++)
            #pragma unroll
            for (int r = 0; r < 4; r++) acc[i][j][r] = 0.f;

    // global->smem mapping
    const int arow  = tid >> 1;              // 0..127
    const int ahalf = (tid & 1) * 16;        // 0/16 cols
    const int bidx  = tid & 127;
    const int brow  = bidx >> 1;             // 0..63
    const int bhalf = (bidx & 1) * 16;
    const bool doBlo = tid >= 128;

    const uint16_t* Bsrc = doBlo ? Blo : Bhi;
    uint16_t*       Bdst = doBlo ? sBl : sBh;

    for (int ch = 0; ch < nChunk; ch++) {
        const int gk = ch * 32;
        // ---- A tiles (hi+lo), 128 rows x 32 cols
        {
            int r = bm + arow;
            uint4 v0 = make_uint4(0, 0, 0, 0), v1 = v0, w0 = v0, w1 = v0;
            if (r < M) {
                const uint4* p = (const uint4*)(Ahi + (size_t)r * KPADMAX + gk + ahalf);
                v0 = p[0]; v1 = p[1];
                const uint4* q = (const uint4*)(Alo + (size_t)r * KPADMAX + gk + ahalf);
                w0 = q[0]; w1 = q[1];
            }
            uint4* d = (uint4*)&sAh[arow * SMST + ahalf];
            d[0] = v0; d[1] = v1;
            uint4* e = (uint4*)&sAl[arow * SMST + ahalf];
            e[0] = w0; e[1] = w1;
        }
        // ---- B tile (hi or lo per thread-half), 64 rows x 32 cols
        {
            const uint4* p = (const uint4*)(Bsrc + (size_t)(bn + brow) * KPADMAX + gk + bhalf);
            uint4 v0 = p[0], v1 = p[1];
            uint4* d = (uint4*)&Bdst[brow * SMST + bhalf];
            d[0] = v0; d[1] = v1;
        }
        __syncthreads();

        #pragma unroll
        for (int ks = 0; ks < 32; ks += 16) {
            const int c0 = ks + 2 * t;
            uint32_t ah[4][4], al[4][4];
            #pragma unroll
            for (int ma = 0; ma < 4; ma++) {
                int r0 = (wm * 64 + ma * 16 + g) * SMST;
                int r1 = r0 + 8 * SMST;
                ah[ma][0] = *(const uint32_t*)&sAh[r0 + c0];
                ah[ma][1] = *(const uint32_t*)&sAh[r1 + c0];
                ah[ma][2] = *(const uint32_t*)&sAh[r0 + c0 + 8];
                ah[ma][3] = *(const uint32_t*)&sAh[r1 + c0 + 8];
                al[ma][0] = *(const uint32_t*)&sAl[r0 + c0];
                al[ma][1] = *(const uint32_t*)&sAl[r1 + c0];
                al[ma][2] = *(const uint32_t*)&sAl[r0 + c0 + 8];
                al[ma][3] = *(const uint32_t*)&sAl[r1 + c0 + 8];
            }
            uint32_t bh[2][2], bl[2][2];
            #pragma unroll
            for (int na = 0; na < 2; na++) {
                int n0 = (wn * 16 + na * 8 + g) * SMST;
                bh[na][0] = *(const uint32_t*)&sBh[n0 + c0];
                bh[na][1] = *(const uint32_t*)&sBh[n0 + c0 + 8];
                bl[na][0] = *(const uint32_t*)&sBl[n0 + c0];
                bl[na][1] = *(const uint32_t*)&sBl[n0 + c0 + 8];
            }
            #pragma unroll
            for (int ma = 0; ma < 4; ma++)
                #pragma unroll
                for (int na = 0; na < 2; na++) {
                    MMA16816(acc[ma][na], ah[ma], bh[na]);
                    MMA16816(acc[ma][na], ah[ma], bl[na]);
                    MMA16816(acc[ma][na], al[ma], bh[na]);
                }
        }
        __syncthreads();
    }

    // epilogue: c0=C[g][2t], c1=C[g][2t+1], c2=C[g+8][2t], c3=C[g+8][2t+1]
    #pragma unroll
    for (int ma = 0; ma < 4; ma++) {
        int r0 = bm + wm * 64 + ma * 16 + g;
        int r1 = r0 + 8;
        #pragma unroll
        for (int na = 0; na < 2; na++) {
            int cc = bn + wn * 16 + na * 8 + 2 * t;
            if (r0 < M)
                *(float2*)&C[(size_t)r0 * HID + cc] = make_float2(acc[ma][na][0], acc[ma][na][1]);
            if (r1 < M)
                *(float2*)&C[(size_t)r1 * HID + cc] = make_float2(acc[ma][na][2], acc[ma][na][3]);
        }
    }
}

// ---------------- tiled fp32 SGEMM (round-5 proven version) ---------------------
#define BM 128
#define BN 64
#define BK 8
#define TM 8
#define TN 4

template<bool EPI_BIAS_RELU>
__global__ void __launch_bounds__(256)
sgemm_kernel(const float* __restrict__ A, const float* __restrict__ B,
             const float* __restrict__ bias, float* __restrict__ C,
             int M, int K, int nc)
{
    __shared__ float As[BK][BM];
    __shared__ float Bs[BK][BN];

    const int tid = threadIdx.x;
    const int bm  = blockIdx.x * BM;
    const int bn  = blockIdx.y * BN;
    const int tx  = tid & 15;
    const int ty  = tid >> 4;

    float acc[TM][TN];
    #pragma unroll
    for (int i = 0; i < TM; i++)
        #pragma unroll
        for (int j = 0; j < TN; j++) acc[i][j] = 0.f;

    const int arow = tid >> 1;
    const int acol = (tid & 1) * 4;
    const int brow = tid >> 5;
    const int bcol = (tid & 31) * 2;

    const bool avalid = (bm + arow) < M;
    const float* Abase = A + (size_t)(bm + arow) * K + acol;
    const float* Bbase = B + (size_t)brow * nc + bn + bcol;

    for (int k0 = 0; k0 < K; k0 += BK) {
        float4 av = make_float4(0.f, 0.f, 0.f, 0.f);
        if (avalid) av = *(const float4*)(Abase + k0);
        As[acol + 0][arow] = av.x;
        As[acol + 1][arow] = av.y;
        As[acol + 2][arow] = av.z;
        As[acol + 3][arow] = av.w;

        float2 bv = *(const float2*)(Bbase + (size_t)k0 * nc);
        Bs[brow][bcol]     = bv.x;
        Bs[brow][bcol + 1] = bv.y;
        __syncthreads();

        #pragma unroll
        for (int kk = 0; kk < BK; kk++) {
            float4 a0 = *(const float4*)&As[kk][ty * TM];
            float4 a1 = *(const float4*)&As[kk][ty * TM + 4];
            float4 b0 = *(const float4*)&Bs[kk][tx * TN];
            float a[TM] = {a0.x, a0.y, a0.z, a0.w, a1.x, a1.y, a1.z, a1.w};
            float b[TN] = {b0.x, b0.y, b0.z, b0.w};
            #pragma unroll
            for (int i = 0; i < TM; i++)
                #pragma unroll
                for (int j = 0; j < TN; j++)
                    acc[i][j] = fmaf(a[i], b[j], acc[i][j]);
        }
        __syncthreads();
    }

    float bv[TN] = {0.f, 0.f, 0.f, 0.f};
    if (EPI_BIAS_RELU) {
        #pragma unroll
        for (int j = 0; j < TN; j++) bv[j] = bias[bn + tx * TN + j];
    }

    #pragma unroll
    for (int i = 0; i < TM; i++) {
        int r = bm + ty * TM + i;
        if (r < M) {
            float4 o;
            float v0 = acc[i][0], v1 = acc[i][1], v2 = acc[i][2], v3 = acc[i][3];
            if (EPI_BIAS_RELU) {
                v0 = fmaxf(v0 + bv[0], 0.f);
                v1 = fmaxf(v1 + bv[1], 0.f);
                v2 = fmaxf(v2 + bv[2], 0.f);
                v3 = fmaxf(v3 + bv[3], 0.f);
            }
            o.x = v0; o.y = v1; o.z = v2; o.w = v3;
            *(float4*)(C + (size_t)r * nc + bn + tx * TN) = o;
        }
    }
}

// =================================================================================
// CSR construction: count -> hierarchical scan (3 kernels) -> scatter
// =================================================================================
__global__ void zero_kernel(int* p, int n)
{
    int i = blockIdx.x * blockDim.x + threadIdx.x;
    if (i < n) p[i] = 0;
}

__global__ void count_kernel(const int* __restrict__ rows, int* __restrict__ cnt, int E)
{
    int e = blockIdx.x * blockDim.x + threadIdx.x;
    if (e < E) atomicAdd(&cnt[rows[e]], 1);
}

__global__ void __launch_bounds__(256)
deg_reduce(const int* __restrict__ cnt, int* __restrict__ bsum, int n)
{
    __shared__ int sh[256];
    int t = threadIdx.x;
    int base = blockIdx.x * 1024 + t * 4;
    int s = 0;
    if (base + 3 < n) {
        int4 v = *(const int4*)(cnt + base);
        s = v.x + v.y + v.z + v.w;
    } else {
        for (int i = 0; i < 4; i++) if (base + i < n) s += cnt[base + i];
    }
    sh[t] = s;
    __syncthreads();
    for (int d = 128; d > 0; d >>= 1) {
        if (t < d) sh[t] += sh[t + d];
        __syncthreads();
    }
    if (t == 0) bsum[blockIdx.x] = sh[0];
}

__global__ void __launch_bounds__(256)
scan_bsums(int* bsum, int nb)
{
    __shared__ int sh[256];
    int t = threadIdx.x;
    int v = (t < nb) ? bsum[t] : 0;
    sh[t] = v;
    __syncthreads();
    for (int d = 1; d < 256; d <<= 1) {
        int u = (t >= d) ? sh[t - d] : 0;
        __syncthreads();
        sh[t] += u;
        __syncthreads();
    }
    if (t < nb) bsum[t] = sh[t] - v;
}

__global__ void __launch_bounds__(256)
scan_apply(const int* __restrict__ cnt, const int* __restrict__ bsum,
           int* __restrict__ off, int* __restrict__ cur, int n, int E)
{
    __shared__ int sh[256];
    int t = threadIdx.x;
    int base = blockIdx.x * 1024 + t * 4;
    int c[4];
    int s = 0;
    #pragma unroll
    for (int i = 0; i < 4; i++) {
        c[i] = (base + i < n) ? cnt[base + i] : 0;
        s += c[i];
    }
    sh[t] = s;
    __syncthreads();
    for (int d = 1; d < 256; d <<= 1) {
        int u = (t >= d) ? sh[t - d] : 0;
        __syncthreads();
        sh[t] += u;
        __syncthreads();
    }
    int pre = bsum[blockIdx.x] + sh[t] - s;
    #pragma unroll
    for (int i = 0; i < 4; i++) {
        if (base + i < n) {
            off[base + i] = pre;
            cur[base + i] = pre;
            pre += c[i];
        }
    }
    if (blockIdx.x == 0 && t == 0) off[n] = E;
}

__global__ void scatter_kernel(const int* __restrict__ rows, const int* __restrict__ cols,
                               const float* __restrict__ vals, int* __restrict__ cur,
                               int* __restrict__ scols, float* __restrict__ svals, int E)
{
    int e = blockIdx.x * blockDim.x + threadIdx.x;
    if (e < E) {
        int p = atomicAdd(&cur[rows[e]], 1);
        scols[p] = cols[e];
        svals[p] = vals[e];
    }
}

// ---------------- row-per-warp SpMM (round-5 proven version) ---------------------
template<int NC, bool RELU>
__global__ void __launch_bounds__(256)
spmm_kernel(const int* __restrict__ off, const int* __restrict__ scols,
            const float* __restrict__ svals, const float* __restrict__ dense,
            const float* __restrict__ bias,
            float* __restrict__ out, int ldo,
            float* __restrict__ out2, int ldo2, int n)
{
    const int warp = (blockIdx.x * blockDim.x + threadIdx.x) >> 5;
    const int lane = threadIdx.x & 31;
    if (warp >= n) return;

    const int s = off[warp];
    const int e = off[warp + 1];
    constexpr int V = NC / 32;

    float acc[V];
    #pragma unroll
    for (int i = 0; i < V; i++) acc[i] = 0.f;

    int j = s;
    for (; j + 1 < e; j += 2) {
        const int   c0 = scols[j],     c1 = scols[j + 1];
        const float v0 = svals[j],     v1 = svals[j + 1];
        const float* d0 = dense + (size_t)c0 * NC;
        const float* d1 = dense + (size_t)c1 * NC;
        #pragma unroll
        for (int i = 0; i < V; i++) {
            acc[i] = fmaf(v0, d0[lane + 32 * i], acc[i]);
            acc[i] = fmaf(v1, d1[lane + 32 * i], acc[i]);
        }
    }
    if (j < e) {
        const int   c = scols[j];
        const float v = svals[j];
        const float* dr = dense + (size_t)c * NC;
        #pragma unroll
        for (int i = 0; i < V; i++)
            acc[i] = fmaf(v, dr[lane + 32 * i], acc[i]);
    }

    #pragma unroll
    for (int i = 0; i < V; i++) {
        float r = acc[i] + bias[lane + 32 * i];
        if (RELU) r = fmaxf(r, 0.f);
        out[(size_t)warp * ldo + lane + 32 * i] = r;
        if (out2) out2[(size_t)warp * ldo2 + lane + 32 * i] = r;
    }
}

// ---------------- DEC soft assignment q ----------------
__global__ void __launch_bounds__(256)
q_kernel(const float* __restrict__ zf, const float* __restrict__ cluster,
         float* __restrict__ q, int n)
{
    __shared__ float cs[KCLUS * EMB];
    for (int i = threadIdx.x; i < KCLUS * EMB; i += blockDim.x) cs[i] = cluster[i];
    __syncthreads();

    int nid = blockIdx.x * blockDim.x + threadIdx.x;
    if (nid >= n) return;

    float z[EMB];
    const float* zr = zf + (size_t)nid * EMB;
    #pragma unroll
    for (int i = 0; i < EMB; i++) z[i] = zr[i];

    float qq[KCLUS];
    float s = 0.f;
    #pragma unroll
    for (int k = 0; k < KCLUS; k++) {
        float d = 0.f;
        #pragma unroll
        for (int i = 0; i < EMB; i++) {
            float diff = z[i] - cs[k * EMB + i];
            d = fmaf(diff, diff, d);
        }
        qq[k] = 1.f / (1.f + d);
        s += qq[k];
    }
    float inv = 1.f / s;
    #pragma unroll
    for (int k = 0; k < KCLUS; k++)
        q[(size_t)nid * KCLUS + k] = qq[k] * inv;
}

// ---------------- host launcher ----------------
extern "C" void kernel_launch(void* const* d_in, const int* in_sizes, int n_in,
                              void* d_out, int out_size)
{
    float *xw, *h, *hw, *zcat, *svals;
    int *cnt, *off, *cur, *scols, *bsum;
    void *xhi, *xlo, *wThi, *wTlo;
    cudaGetSymbolAddress((void**)&xw,    g_xw);
    cudaGetSymbolAddress((void**)&h,     g_h);
    cudaGetSymbolAddress((void**)&hw,    g_hw);
    cudaGetSymbolAddress((void**)&zcat,  g_zcat);
    cudaGetSymbolAddress((void**)&cnt,   g_cnt);
    cudaGetSymbolAddress((void**)&off,   g_off);
    cudaGetSymbolAddress((void**)&cur,   g_cur);
    cudaGetSymbolAddress((void**)&scols, g_scols);
    cudaGetSymbolAddress((void**)&svals, g_svals);
    cudaGetSymbolAddress((void**)&bsum,  g_bsum);
    cudaGetSymbolAddress(&xhi,  g_xhi);
    cudaGetSymbolAddress(&xlo,  g_xlo);
    cudaGetSymbolAddress(&wThi, g_wThi);
    cudaGetSymbolAddress(&wTlo, g_wTlo);

    float* out = (float*)d_out;
    const int N = NNODES;

    // Input ordering detection (dict order vs reference-signature order).
    int IX[3], IR[3], IC[3], IV[3], IW1[3], IB1[3], IW2[3], IB2[3], IFW, IFB, ICL;
    bool dictOrder = (n_in >= 3) && (in_sizes[1] == in_sizes[2]) && (in_sizes[1] < in_sizes[0]);
    if (dictOrder) {
        for (int v = 0; v < 3; v++) {
            IX[v] = 8 * v + 0; IR[v] = 8 * v + 1; IC[v] = 8 * v + 2; IV[v] = 8 * v + 3;
            IW1[v] = 8 * v + 4; IB1[v] = 8 * v + 5; IW2[v] = 8 * v + 6; IB2[v] = 8 * v + 7;
        }
        IFW = 24; IFB = 25; ICL = 26;
    } else {
        for (int v = 0; v < 3; v++) {
            IX[v] = v;
            IR[v] = 3 + 3 * v; IC[v] = 4 + 3 * v; IV[v] = 5 + 3 * v;
            IW1[v] = 12 + 4 * v; IB1[v] = 13 + 4 * v; IW2[v] = 14 + 4 * v; IB2[v] = 15 + 4 * v;
        }
        IFW = 24; IFB = 25; ICL = 26;
    }

    for (int v = 0; v < 3; v++) {
        const float* x    = (const float*)d_in[IX[v]];
        const int*   rows = (const int*)  d_in[IR[v]];
        const int*   cols = (const int*)  d_in[IC[v]];
        const float* vals = (const float*)d_in[IV[v]];
        const float* w1   = (const float*)d_in[IW1[v]];
        const float* b1   = (const float*)d_in[IB1[v]];
        const float* w2   = (const float*)d_in[IW2[v]];
        const float* b2   = (const float*)d_in[IB2[v]];
        const int din = in_sizes[IX[v]] / N;
        const int E   = in_sizes[IR[v]];
        const int nb  = (N + 1023) / 1024;
        const int Kpad   = ((din + 63) / 64) * 64;
        const int nChunk = Kpad / 32;

        // GEMM1 (tensor via mma.sync): split x and w1^T into bf16 hi/lo, 3-pass
        {
            int total = N * (Kpad / 2);
            convx_kernel<<<(total + 255) / 256, 256>>>(x, (__nv_bfloat16*)xhi,
                                                       (__nv_bfloat16*)xlo, N, din, Kpad);
            int wt = HID * Kpad;
            convw_kernel<<<(wt + 255) / 256, 256>>>(w1, (__nv_bfloat16*)wThi,
                                                    (__nv_bfloat16*)wTlo, din, Kpad);
            dim3 grid((N + 127) / 128, HID / 64);
            gemm1_mma<<<grid, 256>>>((const uint16_t*)xhi, (const uint16_t*)xlo,
                                     (const uint16_t*)wThi, (const uint16_t*)wTlo,
                                     xw, N, nChunk);
        }
        // CSR build (hierarchical scan)
        zero_kernel<<<(N + 255) / 256, 256>>>(cnt, N);
        count_kernel<<<(E + 255) / 256, 256>>>(rows, cnt, E);
        deg_reduce<<<nb, 256>>>(cnt, bsum, N);
        scan_bsums<<<1, 256>>>(bsum, nb);
        scan_apply<<<nb, 256>>>(cnt, bsum, off, cur, N, E);
        scatter_kernel<<<(E + 255) / 256, 256>>>(rows, cols, vals, cur, scols, svals, E);
        // SpMM1 + bias + relu -> h [N, HID]
        spmm_kernel<HID, true><<<(N + 7) / 8, 256>>>(off, scols, svals, xw, b1,
                                                     h, HID, nullptr, 0, N);
        // GEMM2: hw = h @ w2  [N, EMB]
        {
            dim3 grid((N + BM - 1) / BM, EMB / BN);
            sgemm_kernel<false><<<grid, 256>>>(h, w2, nullptr, hw, N, HID, EMB);
        }
        // SpMM2 + bias -> z_v, dual-write into d_out and concat buffer
        spmm_kernel<EMB, false><<<(N + 7) / 8, 256>>>(off, scols, svals, hw, b2,
                                                      out + (size_t)v * N * EMB, EMB,
                                                      zcat + (size_t)v * EMB, 3 * EMB, N);
    }

    const float* fw = (const float*)d_in[IFW];
    const float* fb = (const float*)d_in[IFB];
    const float* cl = (const float*)d_in[ICL];
    float* zf = out + (size_t)3 * N * EMB;
    float* qp = out + (size_t)4 * N * EMB;

    // fusion: zf = relu(zcat @ fusion_w + fusion_b)  [N, EMB]
    {
        dim3 grid((N + BM - 1) / BM, EMB / BN);
        sgemm_kernel<true><<<grid, 256>>>(zcat, fw, fb, zf, N, 3 * EMB, EMB);
    }
    // Student-t soft assignment
    q_kernel<<<(N + 255) / 256, 256>>>(zf, cl, qp, N);
}

// round 12
// speedup vs baseline: 2.7096x; 1.0659x over previous
#include <cuda_runtime.h>
#include <cuda_bf16.h>
#include <cstdint>

#define NNODES 50000
#define MAXEDGES 800000
#define HID 128
#define EMB 64
#define KCLUS 10
#define KPADMAX 1024

// ---------------- scratch (device globals; no allocation allowed) ----------------
__device__ float g_xw  [NNODES * HID];
__device__ float g_h   [NNODES * HID];
__device__ float g_hw  [NNODES * EMB];
__device__ float g_zcat[NNODES * 3 * EMB];
__device__ int   g_cnt [NNODES];
__device__ int   g_off [NNODES + 1];
__device__ int   g_cur [NNODES];
__device__ int   g_scols[MAXEDGES];
__device__ float g_svals[MAXEDGES];
__device__ int   g_bsum[64];
__device__ __nv_bfloat16 g_xhi [NNODES * KPADMAX];
__device__ __nv_bfloat16 g_xlo [NNODES * KPADMAX];
__device__ __nv_bfloat16 g_wThi[HID * KPADMAX];
__device__ __nv_bfloat16 g_wTlo[HID * KPADMAX];

// =================================================================================
// fp32 -> bf16 hi/lo split conversion
// =================================================================================
__global__ void __launch_bounds__(256)
convx_kernel(const float* __restrict__ x, __nv_bfloat16* __restrict__ hi,
             __nv_bfloat16* __restrict__ lo, int Mrows, int din, int Kpad)
{
    int idx = blockIdx.x * blockDim.x + threadIdx.x;
    int half = Kpad >> 1;
    if (idx >= Mrows * half) return;
    int row = idx / half;
    int c   = (idx - row * half) * 2;

    float v0 = (c     < din) ? x[(size_t)row * din + c]     : 0.f;
    float v1 = (c + 1 < din) ? x[(size_t)row * din + c + 1] : 0.f;
    __nv_bfloat16 h0 = __float2bfloat16(v0);
    __nv_bfloat16 h1 = __float2bfloat16(v1);
    __nv_bfloat16 l0 = __float2bfloat16(v0 - __bfloat162float(h0));
    __nv_bfloat16 l1 = __float2bfloat16(v1 - __bfloat162float(h1));
    size_t o = (size_t)row * KPADMAX + c;
    *(__nv_bfloat162*)(hi + o) = __nv_bfloat162(h0, h1);
    *(__nv_bfloat162*)(lo + o) = __nv_bfloat162(l0, l1);
}

__global__ void __launch_bounds__(256)
convw_kernel(const float* __restrict__ w1, __nv_bfloat16* __restrict__ hiT,
             __nv_bfloat16* __restrict__ loT, int din, int Kpad)
{
    int idx = blockIdx.x * blockDim.x + threadIdx.x;
    if (idx >= HID * Kpad) return;
    int n = idx / Kpad;
    int k = idx - n * Kpad;
    float v = (k < din) ? w1[(size_t)k * HID + n] : 0.f;
    __nv_bfloat16 h = __float2bfloat16(v);
    __nv_bfloat16 l = __float2bfloat16(v - __bfloat162float(h));
    hiT[(size_t)n * KPADMAX + k] = h;
    loT[(size_t)n * KPADMAX + k] = l;
}

// =================================================================================
// GEMM1 v2: mma.sync m16n8k16 bf16 split hi/lo, ldmatrix fragments,
// cp.async 2-stage pipeline, K-chunk 16.
// CTA tile 128x64; 8 warps wm(2) x wn(4); warp tile 64x16.
// smem row stride 48B (16 bf16 + pad) -> ldmatrix conflict-free.
// =================================================================================
#define SMROW 48                      // bytes per smem row
#define OFF_AH 0
#define OFF_AL 6144
#define OFF_BH 12288
#define OFF_BL 15360
#define STAGE_BYTES 18432

static __device__ __forceinline__ uint32_t smem_u32(const void* p) {
    uint32_t a;
    asm("{ .reg .u64 t; cvta.to.shared.u64 t, %1; cvt.u32.u64 %0, t; }" : "=r"(a) : "l"(p));
    return a;
}

#define CPASYNC16(dst, src, sz) \
    asm volatile("cp.async.ca.shared.global [%0], [%1], 16, %2;" \
                 :: "r"(dst), "l"(src), "r"(sz))
#define CP_COMMIT() asm volatile("cp.async.commit_group;" ::: "memory")
#define CP_WAIT0()  asm volatile("cp.async.wait_group 0;" ::: "memory")
#define CP_WAIT1()  asm volatile("cp.async.wait_group 1;" ::: "memory")

#define LDSM4(r0, r1, r2, r3, addr) \
    asm volatile("ldmatrix.sync.aligned.m8n8.x4.shared.b16 {%0,%1,%2,%3}, [%4];" \
                 : "=r"(r0), "=r"(r1), "=r"(r2), "=r"(r3) : "r"(addr))

#define MMA16816(c, a0, a1, a2, a3, b0, b1)                                   \
    asm volatile(                                                             \
        "mma.sync.aligned.m16n8k16.row.col.f32.bf16.bf16.f32 "                \
        "{%0,%1,%2,%3}, {%4,%5,%6,%7}, {%8,%9}, {%0,%1,%2,%3};"               \
        : "+f"((c)[0]), "+f"((c)[1]), "+f"((c)[2]), "+f"((c)[3])              \
        : "r"(a0), "r"(a1), "r"(a2), "r"(a3), "r"(b0), "r"(b1))

__global__ void __launch_bounds__(256)
gemm1_mma(const __nv_bfloat16* __restrict__ Ahi, const __nv_bfloat16* __restrict__ Alo,
          const __nv_bfloat16* __restrict__ Bhi, const __nv_bfloat16* __restrict__ Blo,
          float* __restrict__ C, int M, int nChunk)
{
    __shared__ __align__(16) uint8_t sm[2][STAGE_BYTES];

    const int tid  = threadIdx.x;
    const int lane = tid & 31;
    const int wid  = tid >> 5;
    const int wm   = wid >> 2;
    const int wn   = wid & 3;
    const int g    = lane >> 2;
    const int t    = lane & 3;
    const int bm   = blockIdx.x * 128;
    const int bn   = blockIdx.y * 64;

    const uint32_t smb = smem_u32(sm);

    float acc[4][2][4];
    #pragma unroll
    for (int i = 0; i < 4; i++)
        #pragma unroll
        for (int j = 0; j < 2; j++)
            #pragma unroll
            for (int r = 0; r < 4; r++) acc[i][j][r] = 0.f;

    // copy mapping
    const int arow = tid >> 1;            // 0..127
    const int ac16 = tid & 1;             // 16B chunk within row
    const int bi   = tid & 127;
    const int brow = bi >> 1;             // 0..63
    const int bc16 = bi & 1;
    const bool doBlo = tid >= 128;
    const __nv_bfloat16* BsrcBase = doBlo ? Blo : Bhi;
    const uint32_t bDstOff = doBlo ? OFF_BL : OFF_BH;

    const int aGr    = bm + arow;
    const bool aOk   = aGr < M;
    const uint32_t aSz = aOk ? 16u : 0u;
    const size_t aRowOff = (size_t)(aOk ? aGr : 0) * KPADMAX + ac16 * 8;
    const size_t bRowOff = (size_t)(bn + brow) * KPADMAX + bc16 * 8;

    auto copyStage = [&](int stg, int ch) {
        const uint32_t sb = smb + stg * STAGE_BYTES;
        const int gk = ch * 16;
        CPASYNC16(sb + OFF_AH + arow * SMROW + ac16 * 16, Ahi + aRowOff + gk, aSz);
        CPASYNC16(sb + OFF_AL + arow * SMROW + ac16 * 16, Alo + aRowOff + gk, aSz);
        CPASYNC16(sb + bDstOff + brow * SMROW + bc16 * 16, BsrcBase + bRowOff + gk, 16u);
    };

    // ldmatrix lane addressing: lanes 0-15 -> rows +lane col 0; 16-31 -> rows +(lane-16) col 16B
    const int lrow = (lane < 16) ? lane : lane - 16;
    const uint32_t lcol = (lane < 16) ? 0 : 16;
    const uint32_t bAddrOff = (uint32_t)(wn * 16 + lrow) * SMROW + lcol;
    const uint32_t aAddrOff = (uint32_t)(wm * 64 + lrow) * SMROW + lcol;

    copyStage(0, 0);
    CP_COMMIT();

    for (int ch = 0; ch < nChunk; ch++) {
        if (ch + 1 < nChunk) {
            copyStage((ch + 1) & 1, ch + 1);
            CP_COMMIT();
            CP_WAIT1();
        } else {
            CP_WAIT0();
        }
        __syncthreads();

        const uint32_t sb = smb + (ch & 1) * STAGE_BYTES;

        uint32_t bh0, bh1, bh2, bh3, bl0, bl1, bl2, bl3;
        LDSM4(bh0, bh1, bh2, bh3, sb + OFF_BH + bAddrOff);
        LDSM4(bl0, bl1, bl2, bl3, sb + OFF_BL + bAddrOff);

        #pragma unroll
        for (int ma = 0; ma < 4; ma++) {
            uint32_t ah0, ah1, ah2, ah3, al0, al1, al2, al3;
            const uint32_t ao = aAddrOff + (uint32_t)(ma * 16) * SMROW;
            LDSM4(ah0, ah1, ah2, ah3, sb + OFF_AH + ao);
            LDSM4(al0, al1, al2, al3, sb + OFF_AL + ao);
            // na=0: b = {m0, m2}; na=1: b = {m1, m3}
            MMA16816(acc[ma][0], ah0, ah1, ah2, ah3, bh0, bh2);
            MMA16816(acc[ma][0], ah0, ah1, ah2, ah3, bl0, bl2);
            MMA16816(acc[ma][0], al0, al1, al2, al3, bh0, bh2);
            MMA16816(acc[ma][1], ah0, ah1, ah2, ah3, bh1, bh3);
            MMA16816(acc[ma][1], ah0, ah1, ah2, ah3, bl1, bl3);
            MMA16816(acc[ma][1], al0, al1, al2, al3, bh1, bh3);
        }
        __syncthreads();
    }

    // epilogue: c0=C[g][2t], c1=C[g][2t+1], c2=C[g+8][2t], c3=C[g+8][2t+1]
    #pragma unroll
    for (int ma = 0; ma < 4; ma++) {
        int r0 = bm + wm * 64 + ma * 16 + g;
        int r1 = r0 + 8;
        #pragma unroll
        for (int na = 0; na < 2; na++) {
            int cc = bn + wn * 16 + na * 8 + 2 * t;
            if (r0 < M)
                *(float2*)&C[(size_t)r0 * HID + cc] = make_float2(acc[ma][na][0], acc[ma][na][1]);
            if (r1 < M)
                *(float2*)&C[(size_t)r1 * HID + cc] = make_float2(acc[ma][na][2], acc[ma][na][3]);
        }
    }
}

// ---------------- tiled fp32 SGEMM (round-5 proven version) ---------------------
#define BM 128
#define BN 64
#define BK 8
#define TM 8
#define TN 4

template<bool EPI_BIAS_RELU>
__global__ void __launch_bounds__(256)
sgemm_kernel(const float* __restrict__ A, const float* __restrict__ B,
             const float* __restrict__ bias, float* __restrict__ C,
             int M, int K, int nc)
{
    __shared__ float As[BK][BM];
    __shared__ float Bs[BK][BN];

    const int tid = threadIdx.x;
    const int bm  = blockIdx.x * BM;
    const int bn  = blockIdx.y * BN;
    const int tx  = tid & 15;
    const int ty  = tid >> 4;

    float acc[TM][TN];
    #pragma unroll
    for (int i = 0; i < TM; i++)
        #pragma unroll
        for (int j = 0; j < TN; j++) acc[i][j] = 0.f;

    const int arow = tid >> 1;
    const int acol = (tid & 1) * 4;
    const int brow = tid >> 5;
    const int bcol = (tid & 31) * 2;

    const bool avalid = (bm + arow) < M;
    const float* Abase = A + (size_t)(bm + arow) * K + acol;
    const float* Bbase = B + (size_t)brow * nc + bn + bcol;

    for (int k0 = 0; k0 < K; k0 += BK) {
        float4 av = make_float4(0.f, 0.f, 0.f, 0.f);
        if (avalid) av = *(const float4*)(Abase + k0);
        As[acol + 0][arow] = av.x;
        As[acol + 1][arow] = av.y;
        As[acol + 2][arow] = av.z;
        As[acol + 3][arow] = av.w;

        float2 bv = *(const float2*)(Bbase + (size_t)k0 * nc);
        Bs[brow][bcol]     = bv.x;
        Bs[brow][bcol + 1] = bv.y;
        __syncthreads();

        #pragma unroll
        for (int kk = 0; kk < BK; kk++) {
            float4 a0 = *(const float4*)&As[kk][ty * TM];
            float4 a1 = *(const float4*)&As[kk][ty * TM + 4];
            float4 b0 = *(const float4*)&Bs[kk][tx * TN];
            float a[TM] = {a0.x, a0.y, a0.z, a0.w, a1.x, a1.y, a1.z, a1.w};
            float b[TN] = {b0.x, b0.y, b0.z, b0.w};
            #pragma unroll
            for (int i = 0; i < TM; i++)
                #pragma unroll
                for (int j = 0; j < TN; j++)
                    acc[i][j] = fmaf(a[i], b[j], acc[i][j]);
        }
        __syncthreads();
    }

    float bv[TN] = {0.f, 0.f, 0.f, 0.f};
    if (EPI_BIAS_RELU) {
        #pragma unroll
        for (int j = 0; j < TN; j++) bv[j] = bias[bn + tx * TN + j];
    }

    #pragma unroll
    for (int i = 0; i < TM; i++) {
        int r = bm + ty * TM + i;
        if (r < M) {
            float4 o;
            float v0 = acc[i][0], v1 = acc[i][1], v2 = acc[i][2], v3 = acc[i][3];
            if (EPI_BIAS_RELU) {
                v0 = fmaxf(v0 + bv[0], 0.f);
                v1 = fmaxf(v1 + bv[1], 0.f);
                v2 = fmaxf(v2 + bv[2], 0.f);
                v3 = fmaxf(v3 + bv[3], 0.f);
            }
            o.x = v0; o.y = v1; o.z = v2; o.w = v3;
            *(float4*)(C + (size_t)r * nc + bn + tx * TN) = o;
        }
    }
}

// =================================================================================
// CSR construction: count -> hierarchical scan -> scatter
// =================================================================================
__global__ void zero_kernel(int* p, int n)
{
    int i = blockIdx.x * blockDim.x + threadIdx.x;
    if (i < n) p[i] = 0;
}

__global__ void count_kernel(const int* __restrict__ rows, int* __restrict__ cnt, int E)
{
    int e = blockIdx.x * blockDim.x + threadIdx.x;
    if (e < E) atomicAdd(&cnt[rows[e]], 1);
}

__global__ void __launch_bounds__(256)
deg_reduce(const int* __restrict__ cnt, int* __restrict__ bsum, int n)
{
    __shared__ int sh[256];
    int t = threadIdx.x;
    int base = blockIdx.x * 1024 + t * 4;
    int s = 0;
    if (base + 3 < n) {
        int4 v = *(const int4*)(cnt + base);
        s = v.x + v.y + v.z + v.w;
    } else {
        for (int i = 0; i < 4; i++) if (base + i < n) s += cnt[base + i];
    }
    sh[t] = s;
    __syncthreads();
    for (int d = 128; d > 0; d >>= 1) {
        if (t < d) sh[t] += sh[t + d];
        __syncthreads();
    }
    if (t == 0) bsum[blockIdx.x] = sh[0];
}

__global__ void __launch_bounds__(256)
scan_bsums(int* bsum, int nb)
{
    __shared__ int sh[256];
    int t = threadIdx.x;
    int v = (t < nb) ? bsum[t] : 0;
    sh[t] = v;
    __syncthreads();
    for (int d = 1; d < 256; d <<= 1) {
        int u = (t >= d) ? sh[t - d] : 0;
        __syncthreads();
        sh[t] += u;
        __syncthreads();
    }
    if (t < nb) bsum[t] = sh[t] - v;
}

__global__ void __launch_bounds__(256)
scan_apply(const int* __restrict__ cnt, const int* __restrict__ bsum,
           int* __restrict__ off, int* __restrict__ cur, int n, int E)
{
    __shared__ int sh[256];
    int t = threadIdx.x;
    int base = blockIdx.x * 1024 + t * 4;
    int c[4];
    int s = 0;
    #pragma unroll
    for (int i = 0; i < 4; i++) {
        c[i] = (base + i < n) ? cnt[base + i] : 0;
        s += c[i];
    }
    sh[t] = s;
    __syncthreads();
    for (int d = 1; d < 256; d <<= 1) {
        int u = (t >= d) ? sh[t - d] : 0;
        __syncthreads();
        sh[t] += u;
        __syncthreads();
    }
    int pre = bsum[blockIdx.x] + sh[t] - s;
    #pragma unroll
    for (int i = 0; i < 4; i++) {
        if (base + i < n) {
            off[base + i] = pre;
            cur[base + i] = pre;
            pre += c[i];
        }
    }
    if (blockIdx.x == 0 && t == 0) off[n] = E;
}

__global__ void scatter_kernel(const int* __restrict__ rows, const int* __restrict__ cols,
                               const float* __restrict__ vals, int* __restrict__ cur,
                               int* __restrict__ scols, float* __restrict__ svals, int E)
{
    int e = blockIdx.x * blockDim.x + threadIdx.x;
    if (e < E) {
        int p = atomicAdd(&cur[rows[e]], 1);
        scols[p] = cols[e];
        svals[p] = vals[e];
    }
}

// ---------------- row-per-warp SpMM, vectorized gathers --------------------------
// lane owns NC/32 CONSECUTIVE cols -> 1 LDG.128 (NC=128) / LDG.64 (NC=64) per edge.
template<int NC, bool RELU>
__global__ void __launch_bounds__(256)
spmm_kernel(const int* __restrict__ off, const int* __restrict__ scols,
            const float* __restrict__ svals, const float* __restrict__ dense,
            const float* __restrict__ bias,
            float* __restrict__ out, int ldo,
            float* __restrict__ out2, int ldo2, int n)
{
    const int warp = (blockIdx.x * blockDim.x + threadIdx.x) >> 5;
    const int lane = threadIdx.x & 31;
    if (warp >= n) return;

    const int s = off[warp];
    const int e = off[warp + 1];
    constexpr int V = NC / 32;
    const int c = lane * V;

    float acc[V];
    #pragma unroll
    for (int i = 0; i < V; i++) acc[i] = 0.f;

    int j = s;
    for (; j + 1 < e; j += 2) {
        const int   c0 = scols[j],     c1 = scols[j + 1];
        const float v0 = svals[j],     v1 = svals[j + 1];
        const float* d0 = dense + (size_t)c0 * NC + c;
        const float* d1 = dense + (size_t)c1 * NC + c;
        if (V == 4) {
            float4 x0 = *(const float4*)d0;
            float4 x1 = *(const float4*)d1;
            acc[0] = fmaf(v0, x0.x, acc[0]); acc[1] = fmaf(v0, x0.y, acc[1]);
            acc[2] = fmaf(v0, x0.z, acc[2]); acc[3] = fmaf(v0, x0.w, acc[3]);
            acc[0] = fmaf(v1, x1.x, acc[0]); acc[1] = fmaf(v1, x1.y, acc[1]);
            acc[2] = fmaf(v1, x1.z, acc[2]); acc[3] = fmaf(v1, x1.w, acc[3]);
        } else {
            float2 x0 = *(const float2*)d0;
            float2 x1 = *(const float2*)d1;
            acc[0] = fmaf(v0, x0.x, acc[0]); acc[1] = fmaf(v0, x0.y, acc[1]);
            acc[0] = fmaf(v1, x1.x, acc[0]); acc[1] = fmaf(v1, x1.y, acc[1]);
        }
    }
    if (j < e) {
        const int   cc = scols[j];
        const float v  = svals[j];
        const float* dr = dense + (size_t)cc * NC + c;
        if (V == 4) {
            float4 x = *(const float4*)dr;
            acc[0] = fmaf(v, x.x, acc[0]); acc[1] = fmaf(v, x.y, acc[1]);
            acc[2] = fmaf(v, x.z, acc[2]); acc[3] = fmaf(v, x.w, acc[3]);
        } else {
            float2 x = *(const float2*)dr;
            acc[0] = fmaf(v, x.x, acc[0]); acc[1] = fmaf(v, x.y, acc[1]);
        }
    }

    float r[V];
    #pragma unroll
    for (int i = 0; i < V; i++) {
        r[i] = acc[i] + bias[c + i];
        if (RELU) r[i] = fmaxf(r[i], 0.f);
    }
    if (V == 4) {
        *(float4*)(out + (size_t)warp * ldo + c) = make_float4(r[0], r[1], r[2], r[3]);
        if (out2)
            *(float4*)(out2 + (size_t)warp * ldo2 + c) = make_float4(r[0], r[1], r[2], r[3]);
    } else {
        *(float2*)(out + (size_t)warp * ldo + c) = make_float2(r[0], r[1]);
        if (out2)
            *(float2*)(out2 + (size_t)warp * ldo2 + c) = make_float2(r[0], r[1]);
    }
}

// ---------------- DEC soft assignment q ----------------
__global__ void __launch_bounds__(256)
q_kernel(const float* __restrict__ zf, const float* __restrict__ cluster,
         float* __restrict__ q, int n)
{
    __shared__ float cs[KCLUS * EMB];
    for (int i = threadIdx.x; i < KCLUS * EMB; i += blockDim.x) cs[i] = cluster[i];
    __syncthreads();

    int nid = blockIdx.x * blockDim.x + threadIdx.x;
    if (nid >= n) return;

    float z[EMB];
    const float* zr = zf + (size_t)nid * EMB;
    #pragma unroll
    for (int i = 0; i < EMB; i++) z[i] = zr[i];

    float qq[KCLUS];
    float s = 0.f;
    #pragma unroll
    for (int k = 0; k < KCLUS; k++) {
        float d = 0.f;
        #pragma unroll
        for (int i = 0; i < EMB; i++) {
            float diff = z[i] - cs[k * EMB + i];
            d = fmaf(diff, diff, d);
        }
        qq[k] = 1.f / (1.f + d);
        s += qq[k];
    }
    float inv = 1.f / s;
    #pragma unroll
    for (int k = 0; k < KCLUS; k++)
        q[(size_t)nid * KCLUS + k] = qq[k] * inv;
}

// ---------------- host launcher ----------------
extern "C" void kernel_launch(void* const* d_in, const int* in_sizes, int n_in,
                              void* d_out, int out_size)
{
    float *xw, *h, *hw, *zcat, *svals;
    int *cnt, *off, *cur, *scols, *bsum;
    void *xhi, *xlo, *wThi, *wTlo;
    cudaGetSymbolAddress((void**)&xw,    g_xw);
    cudaGetSymbolAddress((void**)&h,     g_h);
    cudaGetSymbolAddress((void**)&hw,    g_hw);
    cudaGetSymbolAddress((void**)&zcat,  g_zcat);
    cudaGetSymbolAddress((void**)&cnt,   g_cnt);
    cudaGetSymbolAddress((void**)&off,   g_off);
    cudaGetSymbolAddress((void**)&cur,   g_cur);
    cudaGetSymbolAddress((void**)&scols, g_scols);
    cudaGetSymbolAddress((void**)&svals, g_svals);
    cudaGetSymbolAddress((void**)&bsum,  g_bsum);
    cudaGetSymbolAddress(&xhi,  g_xhi);
    cudaGetSymbolAddress(&xlo,  g_xlo);
    cudaGetSymbolAddress(&wThi, g_wThi);
    cudaGetSymbolAddress(&wTlo, g_wTlo);

    float* out = (float*)d_out;
    const int N = NNODES;

    int IX[3], IR[3], IC[3], IV[3], IW1[3], IB1[3], IW2[3], IB2[3], IFW, IFB, ICL;
    bool dictOrder = (n_in >= 3) && (in_sizes[1] == in_sizes[2]) && (in_sizes[1] < in_sizes[0]);
    if (dictOrder) {
        for (int v = 0; v < 3; v++) {
            IX[v] = 8 * v + 0; IR[v] = 8 * v + 1; IC[v] = 8 * v + 2; IV[v] = 8 * v + 3;
            IW1[v] = 8 * v + 4; IB1[v] = 8 * v + 5; IW2[v] = 8 * v + 6; IB2[v] = 8 * v + 7;
        }
        IFW = 24; IFB = 25; ICL = 26;
    } else {
        for (int v = 0; v < 3; v++) {
            IX[v] = v;
            IR[v] = 3 + 3 * v; IC[v] = 4 + 3 * v; IV[v] = 5 + 3 * v;
            IW1[v] = 12 + 4 * v; IB1[v] = 13 + 4 * v; IW2[v] = 14 + 4 * v; IB2[v] = 15 + 4 * v;
        }
        IFW = 24; IFB = 25; ICL = 26;
    }

    for (int v = 0; v < 3; v++) {
        const float* x    = (const float*)d_in[IX[v]];
        const int*   rows = (const int*)  d_in[IR[v]];
        const int*   cols = (const int*)  d_in[IC[v]];
        const float* vals = (const float*)d_in[IV[v]];
        const float* w1   = (const float*)d_in[IW1[v]];
        const float* b1   = (const float*)d_in[IB1[v]];
        const float* w2   = (const float*)d_in[IW2[v]];
        const float* b2   = (const float*)d_in[IB2[v]];
        const int din = in_sizes[IX[v]] / N;
        const int E   = in_sizes[IR[v]];
        const int nb  = (N + 1023) / 1024;
        const int Kpad   = ((din + 63) / 64) * 64;
        const int nChunk = Kpad / 16;

        // GEMM1 (tensor via mma.sync): split into bf16 hi/lo, ldmatrix + cp.async
        {
            int total = N * (Kpad / 2);
            convx_kernel<<<(total + 255) / 256, 256>>>(x, (__nv_bfloat16*)xhi,
                                                       (__nv_bfloat16*)xlo, N, din, Kpad);
            int wt = HID * Kpad;
            convw_kernel<<<(wt + 255) / 256, 256>>>(w1, (__nv_bfloat16*)wThi,
                                                    (__nv_bfloat16*)wTlo, din, Kpad);
            dim3 grid((N + 127) / 128, HID / 64);
            gemm1_mma<<<grid, 256>>>((const __nv_bfloat16*)xhi, (const __nv_bfloat16*)xlo,
                                     (const __nv_bfloat16*)wThi, (const __nv_bfloat16*)wTlo,
                                     xw, N, nChunk);
        }
        // CSR build
        zero_kernel<<<(N + 255) / 256, 256>>>(cnt, N);
        count_kernel<<<(E + 255) / 256, 256>>>(rows, cnt, E);
        deg_reduce<<<nb, 256>>>(cnt, bsum, N);
        scan_bsums<<<1, 256>>>(bsum, nb);
        scan_apply<<<nb, 256>>>(cnt, bsum, off, cur, N, E);
        scatter_kernel<<<(E + 255) / 256, 256>>>(rows, cols, vals, cur, scols, svals, E);
        // SpMM1 + bias + relu -> h [N, HID]
        spmm_kernel<HID, true><<<(N + 7) / 8, 256>>>(off, scols, svals, xw, b1,
                                                     h, HID, nullptr, 0, N);
        // GEMM2: hw = h @ w2  [N, EMB]
        {
            dim3 grid((N + BM - 1) / BM, EMB / BN);
            sgemm_kernel<false><<<grid, 256>>>(h, w2, nullptr, hw, N, HID, EMB);
        }
        // SpMM2 + bias -> z_v, dual-write
        spmm_kernel<EMB, false><<<(N + 7) / 8, 256>>>(off, scols, svals, hw, b2,
                                                      out + (size_t)v * N * EMB, EMB,
                                                      zcat + (size_t)v * EMB, 3 * EMB, N);
    }

    const float* fw = (const float*)d_in[IFW];
    const float* fb = (const float*)d_in[IFB];
    const float* cl = (const float*)d_in[ICL];
    float* zf = out + (size_t)3 * N * EMB;
    float* qp = out + (size_t)4 * N * EMB;

    {
        dim3 grid((N + BM - 1) / BM, EMB / BN);
        sgemm_kernel<true><<<grid, 256>>>(zcat, fw, fb, zf, N, 3 * EMB, EMB);
    }
    q_kernel<<<(N + 255) / 256, 256>>>(zf, cl, qp, N);
}